// round 11
// baseline (speedup 1.0000x reference)
#include <cuda_runtime.h>
#include <cuda_fp16.h>
#include <cstdint>

#define D      128
#define NMAX   100000
#define TMAX   4
#define CAP    64    // bucket capacity per (type,dst); deg~Poisson(8) -> never exceeded
#define HPAD   24    // half smem row pad: bank (12*lr+lc)%32 all-distinct -> conflict-free

// Scratch: device globals (no runtime allocation allowed). fp16 mantissa (10b)
// == tf32 mantissa, so fp16 storage+MMA matches the measured 3.5e-5 rel_err.
__device__ __half g_H   [(size_t)TMAX * NMAX * D];    // per-type content embeddings
__device__ __half g_slot[(size_t)TMAX * NMAX * D];    // per-type mean-aggregated rows
__device__ int    g_cnt [(size_t)TMAX * NMAX];        // per-type in-degree
__device__ int    g_bucket[(size_t)TMAX * NMAX * CAP];// neighbor src lists

// ---------------------------------------------------------------------------
// Kernel 0: zero counts and d_out.
// ---------------------------------------------------------------------------
__global__ void zero_kernel(float* __restrict__ out, int N, int T) {
    size_t stride = (size_t)gridDim.x * blockDim.x;
    size_t i0 = (size_t)blockIdx.x * blockDim.x + threadIdx.x;
    size_t totalc = (size_t)T * N;
    for (size_t i = i0; i < totalc; i += stride)
        g_cnt[i] = 0;
    if (blockIdx.x == 0 && threadIdx.x < D)
        out[threadIdx.x] = 0.f;
}

// ---------------------------------------------------------------------------
// Kernel 1: per-type content encoder, fp16 MMA (m16n8k16), fp32 accum.
//   H[t][n][o] = LeakyReLU( sum_d x[n][d] * Wc[t][o][d] + bc[t][o] )
// Block 128x128, 8 warps 4(m)x2(n), warp tile 32x64, K=128 in 8 stages of 16.
// B operand: W[o][k] is already the .col fragment's [n][k] layout - no transpose.
// ---------------------------------------------------------------------------
__global__ __launch_bounds__(256) void content_kernel_f16(
    const float* __restrict__ x, const float* __restrict__ Wc,
    const float* __restrict__ bc, int N)
{
    const int t  = blockIdx.y;
    const int m0 = blockIdx.x * 128;
    __shared__ __half a_s[128][HPAD];   // [m][k]
    __shared__ __half b_s[128][HPAD];   // [o][k]
    __shared__ float bias_s[128];

    const float* W = Wc + (size_t)t * D * D;
    const int tid  = threadIdx.x;
    const int wid  = tid >> 5;
    const int lane = tid & 31;
    const int wm   = wid & 3;
    const int wn   = wid >> 2;
    const int lr   = lane >> 2;
    const int lc   = lane & 3;

    if (tid < 128) bias_s[tid] = __ldg(bc + (size_t)t * D + tid);
    __syncthreads();

    float acc[2][8][4];
#pragma unroll
    for (int mi = 0; mi < 2; mi++)
#pragma unroll
        for (int ni = 0; ni < 8; ni++)
#pragma unroll
            for (int c = 0; c < 4; c++) acc[mi][ni][c] = 0.f;

    for (int k0 = 0; k0 < D; k0 += 16) {
#pragma unroll
        for (int q = 0; q < 2; q++) {
            int idx4 = tid * 2 + q;
            int r = idx4 >> 2, c4 = (idx4 & 3) * 4;
            int n = m0 + r;
            float4 v = make_float4(0.f, 0.f, 0.f, 0.f);
            if (n < N) v = *reinterpret_cast<const float4*>(x + (size_t)n * D + k0 + c4);
            *reinterpret_cast<__half2*>(&a_s[r][c4])     = __floats2half2_rn(v.x, v.y);
            *reinterpret_cast<__half2*>(&a_s[r][c4 + 2]) = __floats2half2_rn(v.z, v.w);
            float4 w = *reinterpret_cast<const float4*>(W + (size_t)r * D + k0 + c4);
            *reinterpret_cast<__half2*>(&b_s[r][c4])     = __floats2half2_rn(w.x, w.y);
            *reinterpret_cast<__half2*>(&b_s[r][c4 + 2]) = __floats2half2_rn(w.z, w.w);
        }
        __syncthreads();

        unsigned afrag[2][4];
#pragma unroll
        for (int mi = 0; mi < 2; mi++) {
            int row = wm * 32 + mi * 16 + lr;
            afrag[mi][0] = *reinterpret_cast<const unsigned*>(&a_s[row    ][2 * lc]);
            afrag[mi][1] = *reinterpret_cast<const unsigned*>(&a_s[row + 8][2 * lc]);
            afrag[mi][2] = *reinterpret_cast<const unsigned*>(&a_s[row    ][2 * lc + 8]);
            afrag[mi][3] = *reinterpret_cast<const unsigned*>(&a_s[row + 8][2 * lc + 8]);
        }
        unsigned bfrag[8][2];
#pragma unroll
        for (int ni = 0; ni < 8; ni++) {
            int col = wn * 64 + ni * 8 + lr;
            bfrag[ni][0] = *reinterpret_cast<const unsigned*>(&b_s[col][2 * lc]);
            bfrag[ni][1] = *reinterpret_cast<const unsigned*>(&b_s[col][2 * lc + 8]);
        }
#pragma unroll
        for (int mi = 0; mi < 2; mi++)
#pragma unroll
            for (int ni = 0; ni < 8; ni++) {
                asm volatile(
                    "mma.sync.aligned.m16n8k16.row.col.f32.f16.f16.f32 "
                    "{%0,%1,%2,%3}, {%4,%5,%6,%7}, {%8,%9}, {%0,%1,%2,%3};"
                    : "+f"(acc[mi][ni][0]), "+f"(acc[mi][ni][1]),
                      "+f"(acc[mi][ni][2]), "+f"(acc[mi][ni][3])
                    : "r"(afrag[mi][0]), "r"(afrag[mi][1]),
                      "r"(afrag[mi][2]), "r"(afrag[mi][3]),
                      "r"(bfrag[ni][0]), "r"(bfrag[ni][1]));
            }
        __syncthreads();
    }

    // Epilogue: bias + LeakyReLU, __half2 stores.
    __half* Ht = g_H + (size_t)t * N * D;
#pragma unroll
    for (int mi = 0; mi < 2; mi++) {
        int r0 = m0 + wm * 32 + mi * 16 + lr;
        int r1 = r0 + 8;
#pragma unroll
        for (int ni = 0; ni < 8; ni++) {
            int c0 = wn * 64 + ni * 8 + 2 * lc;
            float b0 = bias_s[c0], b1 = bias_s[c0 + 1];
            if (r0 < N) {
                float y0 = acc[mi][ni][0] + b0, y1 = acc[mi][ni][1] + b1;
                y0 = y0 > 0.f ? y0 : 0.01f * y0;
                y1 = y1 > 0.f ? y1 : 0.01f * y1;
                *reinterpret_cast<__half2*>(Ht + (size_t)r0 * D + c0) = __floats2half2_rn(y0, y1);
            }
            if (r1 < N) {
                float y2 = acc[mi][ni][2] + b0, y3 = acc[mi][ni][3] + b1;
                y2 = y2 > 0.f ? y2 : 0.01f * y2;
                y3 = y3 > 0.f ? y3 : 0.01f * y3;
                *reinterpret_cast<__half2*>(Ht + (size_t)r1 * D + c0) = __floats2half2_rn(y2, y3);
            }
        }
    }
}

// ---------------------------------------------------------------------------
// Kernel 2a: bucket fill (unchanged).
// ---------------------------------------------------------------------------
__global__ __launch_bounds__(256) void fill_kernel(
    const int* __restrict__ esrc, const int* __restrict__ edst,
    int N, int E, int total_edges)
{
    int i = blockIdx.x * 256 + threadIdx.x;
    if (i >= total_edges) return;
    int t = i / E;
    int src = __ldg(esrc + i);
    int dst = __ldg(edst + i);
    size_t idx = (size_t)t * N + dst;
    int pos = atomicAdd(&g_cnt[idx], 1);
    if (pos < CAP) {
        g_bucket[idx * CAP + pos] = src;
    } else {
        const __half* h = g_H + ((size_t)t * N + src) * D;
        __half* sp = g_slot + idx * D;
        for (int j = 0; j < D; j++) atomicAdd(sp + j, h[j]);
    }
}

// ---------------------------------------------------------------------------
// Kernel 2b: gather + normalize. TWO nodes per warp (one per half-warp):
// each lane covers 16B (uint4 = 8 halfs) of the 256B row -> half the load
// instructions of the 8B/lane version. fp32 accumulation.
// ---------------------------------------------------------------------------
__global__ __launch_bounds__(256) void gather_kernel(int N, int total_nodes)
{
    int warp = blockIdx.x * 8 + (threadIdx.x >> 5);
    const int lane = threadIdx.x & 31;
    const int hw = lane >> 4;       // half-warp: 0 or 1
    const int l16 = lane & 15;
    int gw = warp * 2 + hw;
    if (gw >= total_nodes) return;

    int cnt = g_cnt[gw];
    int t = gw / N;
    const __half* Hbase = g_H + (size_t)t * N * D;
    const int* bucket = g_bucket + (size_t)gw * CAP;

    float a[8];
#pragma unroll
    for (int j = 0; j < 8; j++) a[j] = 0.f;

    int m = cnt < CAP ? cnt : CAP;
    int k = 0;
    for (; k + 4 <= m; k += 4) {
        int s[4];
#pragma unroll
        for (int u = 0; u < 4; u++) s[u] = __ldg(bucket + k + u);
        uint4 raw[4];
#pragma unroll
        for (int u = 0; u < 4; u++)
            raw[u] = __ldg(reinterpret_cast<const uint4*>(Hbase + (size_t)s[u] * D) + l16);
#pragma unroll
        for (int u = 0; u < 4; u++) {
            const unsigned* p = &raw[u].x;
#pragma unroll
            for (int h = 0; h < 4; h++) {
                float2 f = __half22float2(*reinterpret_cast<const __half2*>(&p[h]));
                a[2 * h] += f.x; a[2 * h + 1] += f.y;
            }
        }
    }
    for (; k < m; k++) {
        int s = __ldg(bucket + k);
        uint4 raw = __ldg(reinterpret_cast<const uint4*>(Hbase + (size_t)s * D) + l16);
        const unsigned* p = &raw.x;
#pragma unroll
        for (int h = 0; h < 4; h++) {
            float2 f = __half22float2(*reinterpret_cast<const __half2*>(&p[h]));
            a[2 * h] += f.x; a[2 * h + 1] += f.y;
        }
    }
    __half* sp = g_slot + (size_t)gw * D;
    if (cnt > CAP) {
        uint4 raw = *(reinterpret_cast<const uint4*>(sp) + l16);
        const unsigned* p = &raw.x;
#pragma unroll
        for (int h = 0; h < 4; h++) {
            float2 f = __half22float2(*reinterpret_cast<const __half2*>(&p[h]));
            a[2 * h] += f.x; a[2 * h + 1] += f.y;
        }
    }
    float inv = 1.f / fmaxf((float)cnt, 1.f);
    union { uint4 u; __half2 h[4]; } pk;
#pragma unroll
    for (int h = 0; h < 4; h++)
        pk.h[h] = __floats2half2_rn(a[2 * h] * inv, a[2 * h + 1] * inv);
    *(reinterpret_cast<uint4*>(sp) + l16) = pk.u;
}

// ---------------------------------------------------------------------------
// Kernel 3: final GEMM, fp16 MMA (m16n8k16). A staged as raw fp16 copies
// (slot/H already fp16 - zero conversion cost). B (Wa fp32 [k][n]) is
// transpose-staged to b_s[n][k] halfs.  out = mean_n sigmoid(concat @ Wa + ba).
// ---------------------------------------------------------------------------
__global__ __launch_bounds__(256) void final_kernel_f16(
    const float* __restrict__ Wa, const float* __restrict__ ba,
    const int* __restrict__ ntype, float* __restrict__ out, int N, int T)
{
    const int m0 = blockIdx.x * 128;
    __shared__ __half a_s[128][HPAD];   // [m][k]
    __shared__ __half b_s[128][HPAD];   // [n][k] (transposed from Wa[k][n])
    __shared__ int   type_s[128];
    __shared__ float bias_s[128];
    __shared__ float red_s[8][132];

    const int tid  = threadIdx.x;
    const int wid  = tid >> 5;
    const int lane = tid & 31;
    const int wm   = wid & 3;
    const int wn   = wid >> 2;
    const int KTOT = (T + 1) * D;
    const int lr   = lane >> 2;
    const int lc   = lane & 3;

    if (tid < 128) {
        int n = m0 + tid;
        type_s[tid] = (n < N) ? __ldg(ntype + n) : 0;
        bias_s[tid] = __ldg(ba + tid);
    }
    __syncthreads();

    float acc[2][8][4];
#pragma unroll
    for (int mi = 0; mi < 2; mi++)
#pragma unroll
        for (int ni = 0; ni < 8; ni++)
#pragma unroll
            for (int c = 0; c < 4; c++) acc[mi][ni][c] = 0.f;

    for (int k0 = 0; k0 < KTOT; k0 += 16) {
#pragma unroll
        for (int q = 0; q < 2; q++) {
            int idx4 = tid * 2 + q;
            int r = idx4 >> 2, c4 = (idx4 & 3) * 4;   // c4 in halfs
            int n = m0 + r;
            uint2 raw = make_uint2(0u, 0u);
            if (n < N) {
                const __half* src;
                if (k0 < T * D) {
                    int t = k0 >> 7;
                    src = g_slot + (((size_t)t * N + n) << 7) + (k0 & 127) + c4;
                } else {
                    src = g_H + (((size_t)type_s[r] * N + n) << 7) + (k0 - T * D) + c4;
                }
                raw = __ldg(reinterpret_cast<const uint2*>(src));
            }
            *reinterpret_cast<uint2*>(&a_s[r][c4]) = raw;

            // B transpose-stage: Wa[k0+kk][c4b..c4b+3] -> b_s[c4b+j][kk]
            int kk = idx4 >> 5, c4b = (idx4 & 31) * 4;
            float4 w = *reinterpret_cast<const float4*>(Wa + (size_t)(k0 + kk) * D + c4b);
            b_s[c4b + 0][kk] = __float2half(w.x);
            b_s[c4b + 1][kk] = __float2half(w.y);
            b_s[c4b + 2][kk] = __float2half(w.z);
            b_s[c4b + 3][kk] = __float2half(w.w);
        }
        __syncthreads();

        unsigned afrag[2][4];
#pragma unroll
        for (int mi = 0; mi < 2; mi++) {
            int row = wm * 32 + mi * 16 + lr;
            afrag[mi][0] = *reinterpret_cast<const unsigned*>(&a_s[row    ][2 * lc]);
            afrag[mi][1] = *reinterpret_cast<const unsigned*>(&a_s[row + 8][2 * lc]);
            afrag[mi][2] = *reinterpret_cast<const unsigned*>(&a_s[row    ][2 * lc + 8]);
            afrag[mi][3] = *reinterpret_cast<const unsigned*>(&a_s[row + 8][2 * lc + 8]);
        }
        unsigned bfrag[8][2];
#pragma unroll
        for (int ni = 0; ni < 8; ni++) {
            int col = wn * 64 + ni * 8 + lr;
            bfrag[ni][0] = *reinterpret_cast<const unsigned*>(&b_s[col][2 * lc]);
            bfrag[ni][1] = *reinterpret_cast<const unsigned*>(&b_s[col][2 * lc + 8]);
        }
#pragma unroll
        for (int mi = 0; mi < 2; mi++)
#pragma unroll
            for (int ni = 0; ni < 8; ni++) {
                asm volatile(
                    "mma.sync.aligned.m16n8k16.row.col.f32.f16.f16.f32 "
                    "{%0,%1,%2,%3}, {%4,%5,%6,%7}, {%8,%9}, {%0,%1,%2,%3};"
                    : "+f"(acc[mi][ni][0]), "+f"(acc[mi][ni][1]),
                      "+f"(acc[mi][ni][2]), "+f"(acc[mi][ni][3])
                    : "r"(afrag[mi][0]), "r"(afrag[mi][1]),
                      "r"(afrag[mi][2]), "r"(afrag[mi][3]),
                      "r"(bfrag[ni][0]), "r"(bfrag[ni][1]));
            }
        __syncthreads();
    }

    float colsum[8][2];
#pragma unroll
    for (int ni = 0; ni < 8; ni++) { colsum[ni][0] = 0.f; colsum[ni][1] = 0.f; }

#pragma unroll
    for (int mi = 0; mi < 2; mi++) {
        int r0 = m0 + wm * 32 + mi * 16 + lr;
        int r1 = r0 + 8;
        bool ok0 = r0 < N, ok1 = r1 < N;
#pragma unroll
        for (int ni = 0; ni < 8; ni++) {
            int c0 = wn * 64 + ni * 8 + 2 * lc;
            float b0 = bias_s[c0], b1 = bias_s[c0 + 1];
            if (ok0) {
                colsum[ni][0] += 1.f / (1.f + __expf(-(acc[mi][ni][0] + b0)));
                colsum[ni][1] += 1.f / (1.f + __expf(-(acc[mi][ni][1] + b1)));
            }
            if (ok1) {
                colsum[ni][0] += 1.f / (1.f + __expf(-(acc[mi][ni][2] + b0)));
                colsum[ni][1] += 1.f / (1.f + __expf(-(acc[mi][ni][3] + b1)));
            }
        }
    }
#pragma unroll
    for (int ni = 0; ni < 8; ni++)
#pragma unroll
        for (int h = 0; h < 2; h++) {
            float v = colsum[ni][h];
            v += __shfl_xor_sync(0xFFFFFFFF, v, 16);
            v += __shfl_xor_sync(0xFFFFFFFF, v, 8);
            v += __shfl_xor_sync(0xFFFFFFFF, v, 4);
            colsum[ni][h] = v;
        }
    if (lane < 4) {
#pragma unroll
        for (int ni = 0; ni < 8; ni++) {
            int c0 = wn * 64 + ni * 8 + 2 * lane;
            red_s[wid][c0]     = colsum[ni][0];
            red_s[wid][c0 + 1] = colsum[ni][1];
        }
    }
    __syncthreads();
    if (tid < 128) {
        int rbase = (tid >= 64) ? 4 : 0;
        float s = red_s[rbase][tid] + red_s[rbase + 1][tid] +
                  red_s[rbase + 2][tid] + red_s[rbase + 3][tid];
        atomicAdd(out + tid, s * (1.f / (float)N));
    }
}

// ---------------------------------------------------------------------------
// Host launch. Inputs: node_feat, W_content, b_content, W_agg, b_agg,
// edge_src, edge_dst, node_type. Output: float[128].
// ---------------------------------------------------------------------------
extern "C" void kernel_launch(void* const* d_in, const int* in_sizes, int n_in,
                              void* d_out, int out_size)
{
    const float* node_feat = (const float*)d_in[0];
    const float* W_content = (const float*)d_in[1];
    const float* b_content = (const float*)d_in[2];
    const float* W_agg     = (const float*)d_in[3];
    const float* b_agg     = (const float*)d_in[4];
    const int*   edge_src  = (const int*)d_in[5];
    const int*   edge_dst  = (const int*)d_in[6];
    const int*   node_type = (const int*)d_in[7];

    const int N = in_sizes[7];
    const int T = in_sizes[2] / D;
    const int E = in_sizes[5] / T;
    const int total_edges = T * E;
    const int total_nodes = T * N;

    zero_kernel<<<512, 256>>>((float*)d_out, N, T);

    dim3 gA((N + 127) / 128, T);
    content_kernel_f16<<<gA, 256>>>(node_feat, W_content, b_content, N);

    fill_kernel<<<(total_edges + 255) / 256, 256>>>(edge_src, edge_dst, N, E, total_edges);

    int gather_warps = (total_nodes + 1) / 2;
    gather_kernel<<<(gather_warps + 7) / 8, 256>>>(N, total_nodes);

    final_kernel_f16<<<(N + 127) / 128, 256>>>(W_agg, b_agg, node_type, (float*)d_out, N, T);
}